// round 14
// baseline (speedup 1.0000x reference)
#include <cuda_runtime.h>
#include <cuda_fp16.h>
#include <math.h>
#include <stdint.h>

#define BATCH 4
#define NQ    2048
#define NCTX  1024
#define DIMM  1024
#define HEADS 16
#define DHEAD 64
#define FFI   4096
#define KCAT  5120   // 1024 (att) + 4096 (act)
#define NQF   9216   // 8192 (ff1 interleaved) + 1024 (Wq)

// ------------------------- static scratch ---------------------------------
__device__ __align__(1024) __half g_xnh [(size_t)BATCH*NQ*DIMM];
__device__ __align__(1024) __half g_cnh [(size_t)BATCH*NCTX*DIMM];
__device__ __align__(1024) __half g_Qh  [(size_t)BATCH*HEADS*NQ*DHEAD];
__device__ __align__(1024) __half g_Kh  [(size_t)BATCH*NCTX*DHEAD];
__device__ __align__(1024) __half g_Vth [(size_t)BATCH*DHEAD*NCTX];
__device__ __align__(1024) __half g_cat [(size_t)BATCH*NQ*KCAT];   // [att | act]
__device__ __align__(1024) __half g_Wkh [(size_t)2*DHEAD*DIMM];
__device__ __align__(1024) __half g_W1q [(size_t)NQF*DIMM];        // [W1 ilv | Wq]
__device__ __align__(1024) __half g_Wcat[(size_t)DIMM*KCAT];       // [Wo | Wff2]

// ------------------------- helpers ----------------------------------------
__device__ __forceinline__ uint32_t smem_u32(const void* p) {
    uint32_t a;
    asm("{ .reg .u64 t; cvta.to.shared.u64 t, %1; cvt.u32.u64 %0, t; }" : "=r"(a) : "l"(p));
    return a;
}
#define SWZ(x) ((x) ^ (((x) >> 3) & 0x70))
__device__ __forceinline__ void cp16(uint32_t dst, const void* src) {
    asm volatile("cp.async.cg.shared.global [%0], [%1], 16;\n" :: "r"(dst), "l"(src));
}
#define CP_COMMIT() asm volatile("cp.async.commit_group;\n" ::: "memory")
#define CP_WAIT0()  asm volatile("cp.async.wait_group 0;\n"  ::: "memory")
#define CP_WAIT1()  asm volatile("cp.async.wait_group 1;\n"  ::: "memory")
__device__ __forceinline__ void ldsm4(uint32_t* r, uint32_t a) {
    asm volatile("ldmatrix.sync.aligned.m8n8.x4.shared.b16 {%0,%1,%2,%3}, [%4];"
                 : "=r"(r[0]), "=r"(r[1]), "=r"(r[2]), "=r"(r[3]) : "r"(a));
}
__device__ __forceinline__ void mma(float* c, const uint32_t* a, const uint32_t* b) {
    asm volatile("mma.sync.aligned.m16n8k16.row.col.f32.f16.f16.f32 "
                 "{%0,%1,%2,%3}, {%4,%5,%6,%7}, {%8,%9}, {%0,%1,%2,%3};"
                 : "+f"(c[0]), "+f"(c[1]), "+f"(c[2]), "+f"(c[3])
                 : "r"(a[0]), "r"(a[1]), "r"(a[2]), "r"(a[3]), "r"(b[0]), "r"(b[1]));
}

// ------------------------- GEMM (HMMA fp16, 1-term) ------------------------
// C[M x Ntot] = A[M,K] @ B[N,K]^T ; BM=128, BN=128, BK=64, 8 warps,
// 3-stage 32KB ring, 2 CTA/SM. lda/ldb = row strides (elements).
// MODE: 0 f32 store, 1 f32 add, 4 KV epilogue, 7 merged FF1(silu->cat)+Q
template <int MODE>
__global__ void __launch_bounds__(256, 2) gemm_hs(
    const __half* __restrict__ Ah, const __half* __restrict__ Bh,
    float* __restrict__ Cf, int K, int ldn, int lda, int ldb)
{
    constexpr int OFF_BH = 16384;
    constexpr int STAGE  = 32768;
    constexpr int NS     = 3;
    extern __shared__ char smem[];
    uint32_t t0 = smem_u32(smem);
    int tid = threadIdx.x, lane = tid & 31, wid = tid >> 5;

    // L2-friendly supertile rasterization (groups of 8 output-row blocks)
    int bx = blockIdx.x, by = blockIdx.y;
    if ((gridDim.y & 7) == 0) {
        int lin = by * gridDim.x + bx;
        int seg = gridDim.x * 8;
        int band = lin / seg, rem = lin % seg;
        by = band * 8 + (rem & 7);
        bx = rem >> 3;
    }

    size_t rowbase = (size_t)by * 128;
    const __half* As = Ah + rowbase * lda;
    const __half* Bs = Bh + (size_t)bx * 128 * ldb;
    const int nch = K >> 6;

    auto load_chunk = [&](int c, int s) {
        uint32_t st = t0 + s * STAGE;
        int k0 = c << 6;
        #pragma unroll
        for (int u = tid; u < 1024; u += 256) {
            int r = u >> 3, cc = u & 7;
            cp16(st + SWZ(r * 128 + cc * 16), As + (size_t)r * lda + k0 + cc * 8);
        }
        #pragma unroll
        for (int u = tid; u < 1024; u += 256) {
            int r = u >> 3, cc = u & 7;
            cp16(st + OFF_BH + SWZ(r * 128 + cc * 16), Bs + (size_t)r * ldb + k0 + cc * 8);
        }
    };

    for (int p = 0; p < NS - 1; ++p) { if (p < nch) load_chunk(p, p); CP_COMMIT(); }

    float acc[2][8][4] = {};
    int wm = (wid & 3) * 32, wn = (wid >> 2) * 64;
    int arow = lane & 15, aksel = (lane >> 4) * 16;
    int brow = (lane & 7) + ((lane >> 4) & 1) * 8, bksel = ((lane >> 3) & 1) * 16;

    for (int c = 0; c < nch; ++c) {
        CP_WAIT1();
        __syncthreads();
        if (c + NS - 1 < nch) load_chunk(c + NS - 1, (c + NS - 1) % NS);
        CP_COMMIT();
        uint32_t ab = t0 + (c % NS) * STAGE;
        #pragma unroll
        for (int kk = 0; kk < 4; ++kk) {
            uint32_t ahf[2][4], bhf[4][4];
            #pragma unroll
            for (int i = 0; i < 2; ++i)
                ldsm4(ahf[i], ab + SWZ((wm + i * 16 + arow) * 128 + kk * 32 + aksel));
            #pragma unroll
            for (int jf = 0; jf < 4; ++jf)
                ldsm4(bhf[jf], ab + OFF_BH +
                      SWZ((wn + jf * 16 + brow) * 128 + kk * 32 + bksel));
            #pragma unroll
            for (int i = 0; i < 2; ++i)
                #pragma unroll
                for (int j = 0; j < 8; ++j)
                    mma(acc[i][j], ahf[i], &bhf[j >> 1][(j & 1) * 2]);
        }
    }

    int r0l = lane >> 2, cpair = (lane & 3) * 2;
    #pragma unroll
    for (int i = 0; i < 2; ++i)
        #pragma unroll
        for (int j = 0; j < 8; ++j) {
            int colg = bx * 128 + wn + j * 8 + cpair;
            #pragma unroll
            for (int hh2 = 0; hh2 < 2; ++hh2) {
                size_t rowg = rowbase + wm + i * 16 + r0l + hh2 * 8;
                float v0 = acc[i][j][hh2 * 2], v1 = acc[i][j][hh2 * 2 + 1];
                if (MODE == 0) {
                    *(float2*)&Cf[rowg * (size_t)ldn + colg] = make_float2(v0, v1);
                } else if (MODE == 1) {
                    float2* p = (float2*)&Cf[rowg * (size_t)ldn + colg];
                    float2 o = *p; o.x += v0; o.y += v1; *p = o;
                } else if (MODE == 4) {          // KV: K[b,j,d] hi, Vt[b,d,j] hi
                    __half h0 = __float2half_rn(v0), h1 = __float2half_rn(v1);
                    int b = (int)(rowg >> 10), jj = (int)(rowg & 1023);
                    if (colg < 64) {
                        *(half2*)&g_Kh[((size_t)b * NCTX + jj) * DHEAD + colg] =
                            __halves2half2(h0, h1);
                    } else {
                        int d0 = colg - 64;
                        g_Vth[((size_t)b * DHEAD + d0) * NCTX + jj] = h0;
                        g_Vth[((size_t)b * DHEAD + d0 + 1) * NCTX + jj] = h1;
                    }
                } else if (MODE == 7) {          // merged FF1-silu / Q epilogue
                    if (colg < 8192) {           // v0 = h, v1 = gate
                        float a = (v1 / (1.f + __expf(-v1))) * v0;
                        g_cat[rowg * (size_t)KCAT + DIMM + (colg >> 1)] =
                            __float2half_rn(a);
                    } else {
                        int qc = colg - 8192;
                        int b = (int)(rowg >> 11), ii = (int)(rowg & 2047);
                        int hd = qc >> 6, d = qc & 63;
                        size_t o = (((size_t)b * HEADS + hd) * NQ + ii) * DHEAD + d;
                        *(half2*)&g_Qh[o] =
                            __floats2half2_rn(v0 * 0.125f, v1 * 0.125f);
                    }
                }
            }
        }
}

// ------------------------- fused flash attention (1-term) ------------------
__global__ void __launch_bounds__(256, 2) flash_attn(
    const __half* __restrict__ Qh, const __half* __restrict__ Kh,
    const __half* __restrict__ Vt)
{
    extern __shared__ char smem[];
    uint32_t t0 = smem_u32(smem);
    const uint32_t QHO = 0, ST0 = 16384, STSZ = 16384;
    int tid = threadIdx.x, lane = tid & 31, wid = tid >> 5;
    int bh = blockIdx.y, b = bh >> 4, h = bh & 15;
    int i0 = blockIdx.x * 128;
    const __half* Qhp = Qh + (((size_t)b * HEADS + h) * NQ + i0) * DHEAD;
    const __half* Khp = Kh + (size_t)b * NCTX * DHEAD;
    const __half* Vtp = Vt + (size_t)b * DHEAD * NCTX;

    for (int u = tid; u < 128 * 8; u += 256) {
        int r = u >> 3, c = u & 7;
        cp16(t0 + QHO + SWZ(r * 128 + c * 16), Qhp + (size_t)r * DHEAD + c * 8);
    }
    auto load_kv = [&](int t, int s) {
        uint32_t st = t0 + ST0 + s * STSZ;
        int j0 = t * 64;
        for (int u = tid; u < 64 * 8; u += 256) {
            int r = u >> 3, c = u & 7;
            uint32_t d = SWZ(r * 128 + c * 16);
            cp16(st + d,        Khp + (size_t)(j0 + r) * DHEAD + c * 8);
            cp16(st + 8192 + d, Vtp + (size_t)r * NCTX + j0 + c * 8);
        }
    };
    load_kv(0, 0);
    CP_COMMIT();

    float acc_o[8][4] = {};
    float mrow0 = -1e30f, mrow1 = -1e30f, lrow0 = 0.f, lrow1 = 0.f;
    int wm = wid * 16;
    int arow = lane & 15, aksel = (lane >> 4) * 16;
    int brow = (lane & 7) + ((lane >> 4) & 1) * 8, bksel = ((lane >> 3) & 1) * 16;

    for (int t = 0; t < 16; ++t) {
        CP_WAIT0();
        __syncthreads();
        if (t + 1 < 16) load_kv(t + 1, (t + 1) & 1);
        CP_COMMIT();
        uint32_t st = t0 + ST0 + (t & 1) * STSZ;

        float s[8][4] = {};
        #pragma unroll
        for (int kk = 0; kk < 4; ++kk) {
            uint32_t ahf[4];
            ldsm4(ahf, t0 + QHO + SWZ((wm + arow) * 128 + kk * 32 + aksel));
            #pragma unroll
            for (int jf = 0; jf < 4; ++jf) {
                uint32_t bhf[4];
                ldsm4(bhf, st + SWZ((jf * 16 + brow) * 128 + kk * 32 + bksel));
                #pragma unroll
                for (int hf = 0; hf < 2; ++hf)
                    mma(s[jf * 2 + hf], ahf, &bhf[hf * 2]);
            }
        }

        float mx0 = mrow0, mx1 = mrow1;
        #pragma unroll
        for (int nf = 0; nf < 8; ++nf) {
            mx0 = fmaxf(mx0, fmaxf(s[nf][0], s[nf][1]));
            mx1 = fmaxf(mx1, fmaxf(s[nf][2], s[nf][3]));
        }
        mx0 = fmaxf(mx0, __shfl_xor_sync(~0u, mx0, 1));
        mx0 = fmaxf(mx0, __shfl_xor_sync(~0u, mx0, 2));
        mx1 = fmaxf(mx1, __shfl_xor_sync(~0u, mx1, 1));
        mx1 = fmaxf(mx1, __shfl_xor_sync(~0u, mx1, 2));
        float corr0 = __expf(mrow0 - mx0), corr1 = __expf(mrow1 - mx1);
        mrow0 = mx0; mrow1 = mx1;
        float sum0 = 0.f, sum1 = 0.f;
        #pragma unroll
        for (int nf = 0; nf < 8; ++nf) {
            s[nf][0] = __expf(s[nf][0] - mx0); s[nf][1] = __expf(s[nf][1] - mx0);
            s[nf][2] = __expf(s[nf][2] - mx1); s[nf][3] = __expf(s[nf][3] - mx1);
            sum0 += s[nf][0] + s[nf][1]; sum1 += s[nf][2] + s[nf][3];
        }
        sum0 += __shfl_xor_sync(~0u, sum0, 1); sum0 += __shfl_xor_sync(~0u, sum0, 2);
        sum1 += __shfl_xor_sync(~0u, sum1, 1); sum1 += __shfl_xor_sync(~0u, sum1, 2);
        lrow0 = lrow0 * corr0 + sum0;
        lrow1 = lrow1 * corr1 + sum1;
        #pragma unroll
        for (int nf = 0; nf < 8; ++nf) {
            acc_o[nf][0] *= corr0; acc_o[nf][1] *= corr0;
            acc_o[nf][2] *= corr1; acc_o[nf][3] *= corr1;
        }

        uint32_t aph[4][4];
        #pragma unroll
        for (int kf = 0; kf < 4; ++kf)
            #pragma unroll
            for (int q = 0; q < 4; ++q) {
                int nf = kf * 2 + (q >> 1), base = (q & 1) * 2;
                half2 hp = __floats2half2_rn(s[nf][base], s[nf][base + 1]);
                aph[kf][q] = *(uint32_t*)&hp;
            }

        #pragma unroll
        for (int kf = 0; kf < 4; ++kf)
            #pragma unroll
            for (int df = 0; df < 4; ++df) {
                uint32_t bv[4];
                ldsm4(bv, st + 8192 + SWZ((df * 16 + brow) * 128 + kf * 32 + bksel));
                #pragma unroll
                for (int hf = 0; hf < 2; ++hf)
                    mma(acc_o[df * 2 + hf], aph[kf], &bv[hf * 2]);
            }
    }

    float inv0 = 1.f / lrow0, inv1 = 1.f / lrow1;
    int r0 = wm + (lane >> 2), cpair = (lane & 3) * 2;
    #pragma unroll
    for (int nf = 0; nf < 8; ++nf) {
        int d = nf * 8 + cpair;
        size_t o0 = ((size_t)b * NQ + (i0 + r0)) * KCAT + h * DHEAD + d;
        size_t o1 = ((size_t)b * NQ + (i0 + r0 + 8)) * KCAT + h * DHEAD + d;
        *(half2*)&g_cat[o0] = __floats2half2_rn(acc_o[nf][0] * inv0, acc_o[nf][1] * inv0);
        *(half2*)&g_cat[o1] = __floats2half2_rn(acc_o[nf][2] * inv1, acc_o[nf][3] * inv1);
    }
}

// ------------------------- fused LayerNorm (x rows then ctx rows) ---------
__global__ __launch_bounds__(256) void ln_all(
    const float* __restrict__ x, const float* __restrict__ ctx,
    const float* __restrict__ lng, const float* __restrict__ lnb,
    const float* __restrict__ clng, const float* __restrict__ clnb)
{
    int row = blockIdx.x;
    const float* xr;
    const float* g;
    const float* b;
    __half* dst;
    if (row < BATCH * NQ) {
        xr = x + (size_t)row * DIMM; g = lng; b = lnb;
        dst = g_xnh + (size_t)row * DIMM;
    } else {
        int r = row - BATCH * NQ;
        xr = ctx + (size_t)r * DIMM; g = clng; b = clnb;
        dst = g_cnh + (size_t)r * DIMM;
    }
    float s = 0.f, s2 = 0.f;
    for (int c = threadIdx.x; c < DIMM; c += 256) { float v = xr[c]; s += v; s2 += v * v; }
    __shared__ float red[64];
    #pragma unroll
    for (int o = 16; o; o >>= 1) {
        s += __shfl_xor_sync(~0u, s, o); s2 += __shfl_xor_sync(~0u, s2, o);
    }
    int w = threadIdx.x >> 5, l = threadIdx.x & 31;
    if (l == 0) { red[w] = s; red[32 + w] = s2; }
    __syncthreads();
    if (w == 0) {
        s = (l < 8) ? red[l] : 0.f; s2 = (l < 8) ? red[32 + l] : 0.f;
        #pragma unroll
        for (int o = 4; o; o >>= 1) {
            s += __shfl_xor_sync(~0u, s, o); s2 += __shfl_xor_sync(~0u, s2, o);
        }
        if (l == 0) { red[0] = s; red[1] = s2; }
    }
    __syncthreads();
    float mu = red[0] / DIMM, var = red[1] / DIMM - mu * mu, inv = rsqrtf(var + 1e-5f);
    for (int c = threadIdx.x; c < DIMM; c += 256)
        dst[c] = __float2half_rn((xr[c] - mu) * inv * g[c] + b[c]);
}

// ------------------------- fused weight transpose/convert ------------------
__global__ __launch_bounds__(256) void wsplit_all(
    const float* __restrict__ Wq, const float* __restrict__ Wkv,
    const float* __restrict__ Wo, const float* __restrict__ Wff1,
    const float* __restrict__ Wff2)
{
    int t = blockIdx.x;
    const float* W; __half* Bh; int K, N, ilv, dstK;
    if (t < 1024)       { W = Wq;   Bh = g_W1q + (size_t)8192 * DIMM; K = 1024; N = 1024; ilv = 0; dstK = 1024; }
    else if (t < 1152)  { t -= 1024;  W = Wkv;  Bh = g_Wkh;  K = 1024; N = 128;  ilv = 0; dstK = 1024; }
    else if (t < 9344)  { t -= 1152;  W = Wff1; Bh = g_W1q;  K = 1024; N = 8192; ilv = 1; dstK = 1024; }
    else if (t < 10368) { t -= 9344;  W = Wo;   Bh = g_Wcat; K = 1024; N = 1024; ilv = 0; dstK = 5120; }
    else                { t -= 10368; W = Wff2; Bh = g_Wcat + 1024; K = 4096; N = 1024; ilv = 0; dstK = 5120; }
    int nx = N >> 5;
    int n0 = (t % nx) * 32, k0 = (t / nx) * 32;

    __shared__ float tt[32][33];
    int tx = threadIdx.x & 31, ty = threadIdx.x >> 5;
    #pragma unroll
    for (int r = 0; r < 32; r += 8)
        tt[ty + r][tx] = W[(size_t)(k0 + ty + r) * N + n0 + tx];
    __syncthreads();
    #pragma unroll
    for (int r = 0; r < 32; r += 8) {
        float v = tt[tx][ty + r];
        int n = n0 + ty + r;
        int nd = ilv ? ((n < (N >> 1)) ? (n * 2) : ((n - (N >> 1)) * 2 + 1)) : n;
        Bh[(size_t)nd * dstK + k0 + tx] = __float2half_rn(v);
    }
}

// ------------------------- launch -----------------------------------------
static void* sym(const void* s) { void* p = 0; cudaGetSymbolAddress(&p, s); return p; }

extern "C" void kernel_launch(void* const* d_in, const int* in_sizes, int n_in,
                              void* d_out, int out_size)
{
    const float* x    = (const float*)d_in[0];
    const float* ctx  = (const float*)d_in[1];
    const float* lng  = (const float*)d_in[2];
    const float* lnb  = (const float*)d_in[3];
    const float* clng = (const float*)d_in[4];
    const float* clnb = (const float*)d_in[5];
    const float* Wq   = (const float*)d_in[6];
    const float* Wkv  = (const float*)d_in[7];
    const float* Wo   = (const float*)d_in[8];
    const float* Wff1 = (const float*)d_in[9];
    const float* Wff2 = (const float*)d_in[10];
    float* out = (float*)d_out;

    __half *xnh = (__half*)sym(g_xnh), *cnh = (__half*)sym(g_cnh);
    __half *Qh = (__half*)sym(g_Qh), *Kh = (__half*)sym(g_Kh), *Vt = (__half*)sym(g_Vth);
    __half *cat = (__half*)sym(g_cat);
    __half *Wkh = (__half*)sym(g_Wkh);
    __half *W1q = (__half*)sym(g_W1q);
    __half *Wcat = (__half*)sym(g_Wcat);

    const int SMEM1 = 3 * 32768;           // 96 KB GEMM (BM=128, 2 CTA/SM)
    const int FSMEM = 16384 + 2 * 16384;   // 48 KB flash

    static cudaStream_t side = 0;
    static cudaEvent_t evFork = 0, evJoin = 0;
    static int inited = 0;
    if (!inited) {
        inited = 1;
        cudaStreamCreateWithFlags(&side, cudaStreamNonBlocking);
        cudaEventCreateWithFlags(&evFork, cudaEventDisableTiming);
        cudaEventCreateWithFlags(&evJoin, cudaEventDisableTiming);
        cudaFuncSetAttribute(gemm_hs<0>, cudaFuncAttributeMaxDynamicSharedMemorySize, SMEM1);
        cudaFuncSetAttribute(gemm_hs<1>, cudaFuncAttributeMaxDynamicSharedMemorySize, SMEM1);
        cudaFuncSetAttribute(gemm_hs<4>, cudaFuncAttributeMaxDynamicSharedMemorySize, SMEM1);
        cudaFuncSetAttribute(gemm_hs<7>, cudaFuncAttributeMaxDynamicSharedMemorySize, SMEM1);
        cudaFuncSetAttribute(flash_attn, cudaFuncAttributeMaxDynamicSharedMemorySize, FSMEM);
    }

    // 1) all weight prep, one launch
    wsplit_all<<<14464, 256>>>(Wq, Wkv, Wo, Wff1, Wff2);
    // 2) both layernorms, one launch
    ln_all<<<BATCH*NQ + BATCH*NCTX, 256>>>(x, ctx, lng, lnb, clng, clnb);
    // 3) KV = cn@Wkv -> K hi, Vt hi
    gemm_hs<4><<<dim3(1, 32), 256, SMEM1>>>(cnh, Wkh, 0, DIMM, 128, DIMM, DIMM);
    // 4) merged [FF1-silu | Q] GEMM over N=9216
    gemm_hs<7><<<dim3(NQF/128, 64), 256, SMEM1>>>(xnh, W1q, 0, DIMM, NQF, DIMM, DIMM);
    // 5) fork: flash (side) || out1 = act @ Wff2 (main, no flash dependency)
    cudaEventRecord(evFork, 0);
    cudaStreamWaitEvent(side, evFork, 0);
    flash_attn<<<dim3(NQ/128, BATCH*HEADS), 256, FSMEM, side>>>(Qh, Kh, Vt);
    gemm_hs<0><<<dim3(8, 64), 256, SMEM1>>>(cat + DIMM, Wcat + DIMM, out,
                                            4096, DIMM, KCAT, KCAT);
    cudaEventRecord(evJoin, side);
    cudaStreamWaitEvent(0, evJoin, 0);
    // 6) out += att @ Wo  (K=1024)
    gemm_hs<1><<<dim3(8, 64), 256, SMEM1>>>(cat, Wcat, out,
                                            DIMM, DIMM, KCAT, KCAT);
}

// round 16
// speedup vs baseline: 1.0449x; 1.0449x over previous
#include <cuda_runtime.h>
#include <cuda_fp16.h>
#include <math.h>
#include <stdint.h>

#define BATCH 4
#define NQ    2048
#define NCTX  1024
#define DIMM  1024
#define HEADS 16
#define DHEAD 64
#define FFI   4096
#define KCAT  5120   // 1024 (att) + 4096 (act)
#define NQF   9216   // 8192 (ff1 interleaved) + 1024 (Wq)

// ------------------------- static scratch ---------------------------------
__device__ __align__(1024) __half g_xnh [(size_t)BATCH*NQ*DIMM];
__device__ __align__(1024) __half g_cnh [(size_t)BATCH*NCTX*DIMM];
__device__ __align__(1024) __half g_Qh  [(size_t)BATCH*HEADS*NQ*DHEAD];
__device__ __align__(1024) __half g_Kh  [(size_t)BATCH*NCTX*DHEAD];
__device__ __align__(1024) __half g_Vth [(size_t)BATCH*DHEAD*NCTX];
__device__ __align__(1024) __half g_cat [(size_t)BATCH*NQ*KCAT];   // [att | act]
__device__ __align__(1024) __half g_Wkh [(size_t)2*DHEAD*DIMM];
__device__ __align__(1024) __half g_W1q [(size_t)NQF*DIMM];        // [W1 ilv | Wq]
__device__ __align__(1024) __half g_Wcat[(size_t)DIMM*KCAT];       // [Wo | Wff2]

// ------------------------- helpers ----------------------------------------
__device__ __forceinline__ uint32_t smem_u32(const void* p) {
    uint32_t a;
    asm("{ .reg .u64 t; cvta.to.shared.u64 t, %1; cvt.u32.u64 %0, t; }" : "=r"(a) : "l"(p));
    return a;
}
#define SWZ(x) ((x) ^ (((x) >> 3) & 0x70))
__device__ __forceinline__ void cp16(uint32_t dst, const void* src) {
    asm volatile("cp.async.cg.shared.global [%0], [%1], 16;\n" :: "r"(dst), "l"(src));
}
#define CP_COMMIT() asm volatile("cp.async.commit_group;\n" ::: "memory")
#define CP_WAIT0()  asm volatile("cp.async.wait_group 0;\n"  ::: "memory")
#define CP_WAIT1()  asm volatile("cp.async.wait_group 1;\n"  ::: "memory")
__device__ __forceinline__ void ldsm4(uint32_t* r, uint32_t a) {
    asm volatile("ldmatrix.sync.aligned.m8n8.x4.shared.b16 {%0,%1,%2,%3}, [%4];"
                 : "=r"(r[0]), "=r"(r[1]), "=r"(r[2]), "=r"(r[3]) : "r"(a));
}
__device__ __forceinline__ void mma(float* c, const uint32_t* a, const uint32_t* b) {
    asm volatile("mma.sync.aligned.m16n8k16.row.col.f32.f16.f16.f32 "
                 "{%0,%1,%2,%3}, {%4,%5,%6,%7}, {%8,%9}, {%0,%1,%2,%3};"
                 : "+f"(c[0]), "+f"(c[1]), "+f"(c[2]), "+f"(c[3])
                 : "r"(a[0]), "r"(a[1]), "r"(a[2]), "r"(a[3]), "r"(b[0]), "r"(b[1]));
}

// ------------------------- GEMM (HMMA fp16, 1-term) ------------------------
// C[M x Ntot] = A[M,K] @ B[N,K]^T ; BM=128, BN=128, BK=64, 8 warps,
// 3-stage 32KB ring, 2 CTA/SM.
// MODE: 0 f32 store, 4 KV epilogue, 7 merged FF1(silu->cat)+Q epilogue
template <int MODE>
__global__ void __launch_bounds__(256, 2) gemm_hs(
    const __half* __restrict__ Ah, const __half* __restrict__ Bh,
    float* __restrict__ Cf, int K, int ldn)
{
    constexpr int OFF_BH = 16384;
    constexpr int STAGE  = 32768;
    constexpr int NS     = 3;
    extern __shared__ char smem[];
    uint32_t t0 = smem_u32(smem);
    int tid = threadIdx.x, lane = tid & 31, wid = tid >> 5;

    // L2-friendly supertile rasterization (groups of 8 output-row blocks)
    int bx = blockIdx.x, by = blockIdx.y;
    if ((gridDim.y & 7) == 0) {
        int lin = by * gridDim.x + bx;
        int seg = gridDim.x * 8;
        int band = lin / seg, rem = lin % seg;
        by = band * 8 + (rem & 7);
        bx = rem >> 3;
    }

    size_t rowbase = (size_t)by * 128;
    const __half* As = Ah + rowbase * K;
    const __half* Bs = Bh + (size_t)bx * 128 * K;
    const int nch = K >> 6;

    auto load_chunk = [&](int c, int s) {
        uint32_t st = t0 + s * STAGE;
        int k0 = c << 6;
        #pragma unroll
        for (int u = tid; u < 1024; u += 256) {
            int r = u >> 3, cc = u & 7;
            cp16(st + SWZ(r * 128 + cc * 16), As + (size_t)r * K + k0 + cc * 8);
        }
        #pragma unroll
        for (int u = tid; u < 1024; u += 256) {
            int r = u >> 3, cc = u & 7;
            cp16(st + OFF_BH + SWZ(r * 128 + cc * 16), Bs + (size_t)r * K + k0 + cc * 8);
        }
    };

    for (int p = 0; p < NS - 1; ++p) { if (p < nch) load_chunk(p, p); CP_COMMIT(); }

    float acc[2][8][4] = {};
    int wm = (wid & 3) * 32, wn = (wid >> 2) * 64;
    int arow = lane & 15, aksel = (lane >> 4) * 16;
    int brow = (lane & 7) + ((lane >> 4) & 1) * 8, bksel = ((lane >> 3) & 1) * 16;

    for (int c = 0; c < nch; ++c) {
        CP_WAIT1();
        __syncthreads();
        if (c + NS - 1 < nch) load_chunk(c + NS - 1, (c + NS - 1) % NS);
        CP_COMMIT();
        uint32_t ab = t0 + (c % NS) * STAGE;
        #pragma unroll
        for (int kk = 0; kk < 4; ++kk) {
            uint32_t ahf[2][4], bhf[4][4];
            #pragma unroll
            for (int i = 0; i < 2; ++i)
                ldsm4(ahf[i], ab + SWZ((wm + i * 16 + arow) * 128 + kk * 32 + aksel));
            #pragma unroll
            for (int jf = 0; jf < 4; ++jf)
                ldsm4(bhf[jf], ab + OFF_BH +
                      SWZ((wn + jf * 16 + brow) * 128 + kk * 32 + bksel));
            #pragma unroll
            for (int i = 0; i < 2; ++i)
                #pragma unroll
                for (int j = 0; j < 8; ++j)
                    mma(acc[i][j], ahf[i], &bhf[j >> 1][(j & 1) * 2]);
        }
    }

    int r0l = lane >> 2, cpair = (lane & 3) * 2;
    #pragma unroll
    for (int i = 0; i < 2; ++i)
        #pragma unroll
        for (int j = 0; j < 8; ++j) {
            int colg = bx * 128 + wn + j * 8 + cpair;
            #pragma unroll
            for (int hh2 = 0; hh2 < 2; ++hh2) {
                size_t rowg = rowbase + wm + i * 16 + r0l + hh2 * 8;
                float v0 = acc[i][j][hh2 * 2], v1 = acc[i][j][hh2 * 2 + 1];
                if (MODE == 0) {
                    *(float2*)&Cf[rowg * (size_t)ldn + colg] = make_float2(v0, v1);
                } else if (MODE == 4) {          // KV: K[b,j,d] hi, Vt[b,d,j] hi
                    __half h0 = __float2half_rn(v0), h1 = __float2half_rn(v1);
                    int b = (int)(rowg >> 10), jj = (int)(rowg & 1023);
                    if (colg < 64) {
                        *(half2*)&g_Kh[((size_t)b * NCTX + jj) * DHEAD + colg] =
                            __halves2half2(h0, h1);
                    } else {
                        int d0 = colg - 64;
                        g_Vth[((size_t)b * DHEAD + d0) * NCTX + jj] = h0;
                        g_Vth[((size_t)b * DHEAD + d0 + 1) * NCTX + jj] = h1;
                    }
                } else if (MODE == 7) {          // merged FF1-silu / Q epilogue
                    if (colg < 8192) {           // v0 = h, v1 = gate
                        float a = (v1 / (1.f + __expf(-v1))) * v0;
                        g_cat[rowg * (size_t)KCAT + DIMM + (colg >> 1)] =
                            __float2half_rn(a);
                    } else {
                        int qc = colg - 8192;
                        int b = (int)(rowg >> 11), ii = (int)(rowg & 2047);
                        int hd = qc >> 6, d = qc & 63;
                        size_t o = (((size_t)b * HEADS + hd) * NQ + ii) * DHEAD + d;
                        *(half2*)&g_Qh[o] =
                            __floats2half2_rn(v0 * 0.125f, v1 * 0.125f);
                    }
                }
            }
        }
}

// ------------------------- fused flash attention (1-term) ------------------
__global__ void __launch_bounds__(256, 2) flash_attn(
    const __half* __restrict__ Qh, const __half* __restrict__ Kh,
    const __half* __restrict__ Vt)
{
    extern __shared__ char smem[];
    uint32_t t0 = smem_u32(smem);
    const uint32_t QHO = 0, ST0 = 16384, STSZ = 16384;
    int tid = threadIdx.x, lane = tid & 31, wid = tid >> 5;
    int bh = blockIdx.y, b = bh >> 4, h = bh & 15;
    int i0 = blockIdx.x * 128;
    const __half* Qhp = Qh + (((size_t)b * HEADS + h) * NQ + i0) * DHEAD;
    const __half* Khp = Kh + (size_t)b * NCTX * DHEAD;
    const __half* Vtp = Vt + (size_t)b * DHEAD * NCTX;

    for (int u = tid; u < 128 * 8; u += 256) {
        int r = u >> 3, c = u & 7;
        cp16(t0 + QHO + SWZ(r * 128 + c * 16), Qhp + (size_t)r * DHEAD + c * 8);
    }
    auto load_kv = [&](int t, int s) {
        uint32_t st = t0 + ST0 + s * STSZ;
        int j0 = t * 64;
        for (int u = tid; u < 64 * 8; u += 256) {
            int r = u >> 3, c = u & 7;
            uint32_t d = SWZ(r * 128 + c * 16);
            cp16(st + d,        Khp + (size_t)(j0 + r) * DHEAD + c * 8);
            cp16(st + 8192 + d, Vtp + (size_t)r * NCTX + j0 + c * 8);
        }
    };
    load_kv(0, 0);
    CP_COMMIT();

    float acc_o[8][4] = {};
    float mrow0 = -1e30f, mrow1 = -1e30f, lrow0 = 0.f, lrow1 = 0.f;
    int wm = wid * 16;
    int arow = lane & 15, aksel = (lane >> 4) * 16;
    int brow = (lane & 7) + ((lane >> 4) & 1) * 8, bksel = ((lane >> 3) & 1) * 16;

    for (int t = 0; t < 16; ++t) {
        CP_WAIT0();
        __syncthreads();
        if (t + 1 < 16) load_kv(t + 1, (t + 1) & 1);
        CP_COMMIT();
        uint32_t st = t0 + ST0 + (t & 1) * STSZ;

        float s[8][4] = {};
        #pragma unroll
        for (int kk = 0; kk < 4; ++kk) {
            uint32_t ahf[4];
            ldsm4(ahf, t0 + QHO + SWZ((wm + arow) * 128 + kk * 32 + aksel));
            #pragma unroll
            for (int jf = 0; jf < 4; ++jf) {
                uint32_t bhf[4];
                ldsm4(bhf, st + SWZ((jf * 16 + brow) * 128 + kk * 32 + bksel));
                #pragma unroll
                for (int hf = 0; hf < 2; ++hf)
                    mma(s[jf * 2 + hf], ahf, &bhf[hf * 2]);
            }
        }

        float mx0 = mrow0, mx1 = mrow1;
        #pragma unroll
        for (int nf = 0; nf < 8; ++nf) {
            mx0 = fmaxf(mx0, fmaxf(s[nf][0], s[nf][1]));
            mx1 = fmaxf(mx1, fmaxf(s[nf][2], s[nf][3]));
        }
        mx0 = fmaxf(mx0, __shfl_xor_sync(~0u, mx0, 1));
        mx0 = fmaxf(mx0, __shfl_xor_sync(~0u, mx0, 2));
        mx1 = fmaxf(mx1, __shfl_xor_sync(~0u, mx1, 1));
        mx1 = fmaxf(mx1, __shfl_xor_sync(~0u, mx1, 2));
        float corr0 = __expf(mrow0 - mx0), corr1 = __expf(mrow1 - mx1);
        mrow0 = mx0; mrow1 = mx1;
        float sum0 = 0.f, sum1 = 0.f;
        #pragma unroll
        for (int nf = 0; nf < 8; ++nf) {
            s[nf][0] = __expf(s[nf][0] - mx0); s[nf][1] = __expf(s[nf][1] - mx0);
            s[nf][2] = __expf(s[nf][2] - mx1); s[nf][3] = __expf(s[nf][3] - mx1);
            sum0 += s[nf][0] + s[nf][1]; sum1 += s[nf][2] + s[nf][3];
        }
        sum0 += __shfl_xor_sync(~0u, sum0, 1); sum0 += __shfl_xor_sync(~0u, sum0, 2);
        sum1 += __shfl_xor_sync(~0u, sum1, 1); sum1 += __shfl_xor_sync(~0u, sum1, 2);
        lrow0 = lrow0 * corr0 + sum0;
        lrow1 = lrow1 * corr1 + sum1;
        #pragma unroll
        for (int nf = 0; nf < 8; ++nf) {
            acc_o[nf][0] *= corr0; acc_o[nf][1] *= corr0;
            acc_o[nf][2] *= corr1; acc_o[nf][3] *= corr1;
        }

        uint32_t aph[4][4];
        #pragma unroll
        for (int kf = 0; kf < 4; ++kf)
            #pragma unroll
            for (int q = 0; q < 4; ++q) {
                int nf = kf * 2 + (q >> 1), base = (q & 1) * 2;
                half2 hp = __floats2half2_rn(s[nf][base], s[nf][base + 1]);
                aph[kf][q] = *(uint32_t*)&hp;
            }

        #pragma unroll
        for (int kf = 0; kf < 4; ++kf)
            #pragma unroll
            for (int df = 0; df < 4; ++df) {
                uint32_t bv[4];
                ldsm4(bv, st + 8192 + SWZ((df * 16 + brow) * 128 + kf * 32 + bksel));
                #pragma unroll
                for (int hf = 0; hf < 2; ++hf)
                    mma(acc_o[df * 2 + hf], aph[kf], &bv[hf * 2]);
            }
    }

    float inv0 = 1.f / lrow0, inv1 = 1.f / lrow1;
    int r0 = wm + (lane >> 2), cpair = (lane & 3) * 2;
    #pragma unroll
    for (int nf = 0; nf < 8; ++nf) {
        int d = nf * 8 + cpair;
        size_t o0 = ((size_t)b * NQ + (i0 + r0)) * KCAT + h * DHEAD + d;
        size_t o1 = ((size_t)b * NQ + (i0 + r0 + 8)) * KCAT + h * DHEAD + d;
        *(half2*)&g_cat[o0] = __floats2half2_rn(acc_o[nf][0] * inv0, acc_o[nf][1] * inv0);
        *(half2*)&g_cat[o1] = __floats2half2_rn(acc_o[nf][2] * inv1, acc_o[nf][3] * inv1);
    }
}

// ------------------------- fused LayerNorm (x rows then ctx rows) ---------
__global__ __launch_bounds__(256) void ln_all(
    const float* __restrict__ x, const float* __restrict__ ctx,
    const float* __restrict__ lng, const float* __restrict__ lnb,
    const float* __restrict__ clng, const float* __restrict__ clnb)
{
    int row = blockIdx.x;
    const float* xr;
    const float* g;
    const float* b;
    __half* dst;
    if (row < BATCH * NQ) {
        xr = x + (size_t)row * DIMM; g = lng; b = lnb;
        dst = g_xnh + (size_t)row * DIMM;
    } else {
        int r = row - BATCH * NQ;
        xr = ctx + (size_t)r * DIMM; g = clng; b = clnb;
        dst = g_cnh + (size_t)r * DIMM;
    }
    float s = 0.f, s2 = 0.f;
    for (int c = threadIdx.x; c < DIMM; c += 256) { float v = xr[c]; s += v; s2 += v * v; }
    __shared__ float red[64];
    #pragma unroll
    for (int o = 16; o; o >>= 1) {
        s += __shfl_xor_sync(~0u, s, o); s2 += __shfl_xor_sync(~0u, s2, o);
    }
    int w = threadIdx.x >> 5, l = threadIdx.x & 31;
    if (l == 0) { red[w] = s; red[32 + w] = s2; }
    __syncthreads();
    if (w == 0) {
        s = (l < 8) ? red[l] : 0.f; s2 = (l < 8) ? red[32 + l] : 0.f;
        #pragma unroll
        for (int o = 4; o; o >>= 1) {
            s += __shfl_xor_sync(~0u, s, o); s2 += __shfl_xor_sync(~0u, s2, o);
        }
        if (l == 0) { red[0] = s; red[1] = s2; }
    }
    __syncthreads();
    float mu = red[0] / DIMM, var = red[1] / DIMM - mu * mu, inv = rsqrtf(var + 1e-5f);
    for (int c = threadIdx.x; c < DIMM; c += 256)
        dst[c] = __float2half_rn((xr[c] - mu) * inv * g[c] + b[c]);
}

// ------------------------- fused weight transpose/convert ------------------
__global__ __launch_bounds__(256) void wsplit_all(
    const float* __restrict__ Wq, const float* __restrict__ Wkv,
    const float* __restrict__ Wo, const float* __restrict__ Wff1,
    const float* __restrict__ Wff2)
{
    int t = blockIdx.x;
    const float* W; __half* Bh; int K, N, ilv, dstK;
    if (t < 1024)       { W = Wq;   Bh = g_W1q + (size_t)8192 * DIMM; K = 1024; N = 1024; ilv = 0; dstK = 1024; }
    else if (t < 1152)  { t -= 1024;  W = Wkv;  Bh = g_Wkh;  K = 1024; N = 128;  ilv = 0; dstK = 1024; }
    else if (t < 9344)  { t -= 1152;  W = Wff1; Bh = g_W1q;  K = 1024; N = 8192; ilv = 1; dstK = 1024; }
    else if (t < 10368) { t -= 9344;  W = Wo;   Bh = g_Wcat; K = 1024; N = 1024; ilv = 0; dstK = 5120; }
    else                { t -= 10368; W = Wff2; Bh = g_Wcat + 1024; K = 4096; N = 1024; ilv = 0; dstK = 5120; }
    int nx = N >> 5;
    int n0 = (t % nx) * 32, k0 = (t / nx) * 32;

    __shared__ float tt[32][33];
    int tx = threadIdx.x & 31, ty = threadIdx.x >> 5;
    #pragma unroll
    for (int r = 0; r < 32; r += 8)
        tt[ty + r][tx] = W[(size_t)(k0 + ty + r) * N + n0 + tx];
    __syncthreads();
    #pragma unroll
    for (int r = 0; r < 32; r += 8) {
        float v = tt[tx][ty + r];
        int n = n0 + ty + r;
        int nd = ilv ? ((n < (N >> 1)) ? (n * 2) : ((n - (N >> 1)) * 2 + 1)) : n;
        Bh[(size_t)nd * dstK + k0 + tx] = __float2half_rn(v);
    }
}

// ------------------------- launch -----------------------------------------
static void* sym(const void* s) { void* p = 0; cudaGetSymbolAddress(&p, s); return p; }

extern "C" void kernel_launch(void* const* d_in, const int* in_sizes, int n_in,
                              void* d_out, int out_size)
{
    const float* x    = (const float*)d_in[0];
    const float* ctx  = (const float*)d_in[1];
    const float* lng  = (const float*)d_in[2];
    const float* lnb  = (const float*)d_in[3];
    const float* clng = (const float*)d_in[4];
    const float* clnb = (const float*)d_in[5];
    const float* Wq   = (const float*)d_in[6];
    const float* Wkv  = (const float*)d_in[7];
    const float* Wo   = (const float*)d_in[8];
    const float* Wff1 = (const float*)d_in[9];
    const float* Wff2 = (const float*)d_in[10];
    float* out = (float*)d_out;

    __half *xnh = (__half*)sym(g_xnh), *cnh = (__half*)sym(g_cnh);
    __half *Qh = (__half*)sym(g_Qh), *Kh = (__half*)sym(g_Kh), *Vt = (__half*)sym(g_Vth);
    __half *cat = (__half*)sym(g_cat);
    __half *Wkh = (__half*)sym(g_Wkh);
    __half *W1q = (__half*)sym(g_W1q);
    __half *Wcat = (__half*)sym(g_Wcat);

    const int SMEM1 = 3 * 32768;           // 96 KB GEMM (BM=128, 2 CTA/SM)
    const int FSMEM = 16384 + 2 * 16384;   // 48 KB flash

    static cudaStream_t side = 0;
    static cudaEvent_t evS = 0, evW = 0, evL = 0, evG7 = 0, evF = 0;
    static int inited = 0;
    if (!inited) {
        inited = 1;
        cudaStreamCreateWithFlags(&side, cudaStreamNonBlocking);
        cudaEventCreateWithFlags(&evS,  cudaEventDisableTiming);
        cudaEventCreateWithFlags(&evW,  cudaEventDisableTiming);
        cudaEventCreateWithFlags(&evL,  cudaEventDisableTiming);
        cudaEventCreateWithFlags(&evG7, cudaEventDisableTiming);
        cudaEventCreateWithFlags(&evF,  cudaEventDisableTiming);
        cudaFuncSetAttribute(gemm_hs<0>, cudaFuncAttributeMaxDynamicSharedMemorySize, SMEM1);
        cudaFuncSetAttribute(gemm_hs<4>, cudaFuncAttributeMaxDynamicSharedMemorySize, SMEM1);
        cudaFuncSetAttribute(gemm_hs<7>, cudaFuncAttributeMaxDynamicSharedMemorySize, SMEM1);
        cudaFuncSetAttribute(flash_attn, cudaFuncAttributeMaxDynamicSharedMemorySize, FSMEM);
    }

    // Fork: side must join the capture via an event from the origin stream
    cudaEventRecord(evS, 0);
    cudaStreamWaitEvent(side, evS, 0);

    // 1) wsplit (side)  ||  ln (main)   — fully independent
    wsplit_all<<<14464, 256, 0, side>>>(Wq, Wkv, Wo, Wff1, Wff2);
    ln_all<<<BATCH*NQ + BATCH*NCTX, 256>>>(x, ctx, lng, lnb, clng, clnb);
    // cross-sync: main gets wsplit, side gets ln
    cudaEventRecord(evW, side);
    cudaStreamWaitEvent(0, evW, 0);
    cudaEventRecord(evL, 0);
    cudaStreamWaitEvent(side, evL, 0);

    // 2) gemm7 (main)  ||  KV (side)    — same resource shape, co-resident
    gemm_hs<7><<<dim3(NQF/128, 64), 256, SMEM1>>>(xnh, W1q, 0, DIMM, NQF);
    cudaEventRecord(evG7, 0);
    gemm_hs<4><<<dim3(1, 32), 256, SMEM1, side>>>(cnh, Wkh, 0, DIMM, 128);

    // 3) flash on side (needs Q from gemm7 and K/V)
    cudaStreamWaitEvent(side, evG7, 0);
    flash_attn<<<dim3(NQ/128, BATCH*HEADS), 256, FSMEM, side>>>(Qh, Kh, Vt);
    cudaEventRecord(evF, side);
    cudaStreamWaitEvent(0, evF, 0);

    // 4) out = cat @ Wcat^T (K=5120)
    gemm_hs<0><<<dim3(8, 64), 256, SMEM1>>>(cat, Wcat, out, KCAT, DIMM);
}